// round 12
// baseline (speedup 1.0000x reference)
#include <cuda_runtime.h>
#include <cuda_bf16.h>
#include <cstdint>

#define N_NODES 50000
#define N_EDGES 640000
#define HID 128
#define KSTR 136                     // padded k-stride (bf16 elems)
#define KSTRB (KSTR * 2)             // 272 bytes
#define TILE_B (128 * KSTRB)         // 34816 bytes per 128-row bf16 tile
#define NBLK 196                     // ceil(N_NODES/256)

// ---------------- scratch (static __device__; no allocations) --------------
__device__ float4 g_aggr4[(size_t)N_NODES * (HID / 4)];
__device__ float4 g_proj4[16 * (HID / 4)];
__device__ int    g_idx64;
__device__ int    g_cnt[N_NODES];
__device__ int    g_off[N_NODES + 1];
__device__ int    g_cur[N_NODES];
__device__ int    g_bsum[256];
__device__ int    g_barA, g_barB, g_barC;
__device__ int      g_dst[N_EDGES];
__device__ unsigned g_srch[N_EDGES];     // (src << 4) | h
__device__ unsigned g_packed[N_EDGES];   // dst-sorted (src << 4) | h
// bf16 hi/lo weight tiles, transposed [n][k], stride KSTR
__device__ __align__(16) unsigned short g_w1h[128 * KSTR];
__device__ __align__(16) unsigned short g_w1l[128 * KSTR];
__device__ __align__(16) unsigned short g_w2h[128 * KSTR];
__device__ __align__(16) unsigned short g_w2l[128 * KSTR];

// ---------------- helpers ---------------------------------------------------
__device__ __forceinline__ uint32_t smem_u32(const void* p) {
    uint32_t a;
    asm("{ .reg .u64 t; cvta.to.shared.u64 t, %1; cvt.u32.u64 %0, t; }"
        : "=r"(a) : "l"(p));
    return a;
}
__device__ __forceinline__ void ldsm4(uint32_t* r, uint32_t a) {
    asm volatile("ldmatrix.sync.aligned.m8n8.x4.shared.b16 {%0,%1,%2,%3}, [%4];"
                 : "=r"(r[0]), "=r"(r[1]), "=r"(r[2]), "=r"(r[3]) : "r"(a));
}
__device__ __forceinline__ void mma_bf16(float* d, const uint32_t* a,
                                         uint32_t b0, uint32_t b1) {
    asm volatile(
        "mma.sync.aligned.m16n8k16.row.col.f32.bf16.bf16.f32 "
        "{%0,%1,%2,%3}, {%4,%5,%6,%7}, {%8,%9}, {%0,%1,%2,%3};"
        : "+f"(d[0]), "+f"(d[1]), "+f"(d[2]), "+f"(d[3])
        : "r"(a[0]), "r"(a[1]), "r"(a[2]), "r"(a[3]), "r"(b0), "r"(b1));
}
__device__ __forceinline__ uint32_t splitpair(float v0, float v1, uint32_t& lo) {
    __nv_bfloat16 h0 = __float2bfloat16(v0), h1 = __float2bfloat16(v1);
    __nv_bfloat16 l0 = __float2bfloat16(v0 - __bfloat162float(h0));
    __nv_bfloat16 l1 = __float2bfloat16(v1 - __bfloat162float(h1));
    lo = (uint32_t)__bfloat16_as_ushort(l0) |
         ((uint32_t)__bfloat16_as_ushort(l1) << 16);
    return (uint32_t)__bfloat16_as_ushort(h0) |
           ((uint32_t)__bfloat16_as_ushort(h1) << 16);
}
__device__ __forceinline__ void grid_barrier(int* bar) {
    __syncthreads();
    if (threadIdx.x == 0) {
        __threadfence();
        atomicAdd(bar, 1);
        while (atomicAdd(bar, 0) < NBLK) { }
        __threadfence();
    }
    __syncthreads();
}

// ---------------------------------------------------------------------------
// setup: blocks 0..195 zero counts (+ block0 probe + barrier reset),
//        blocks 196..203 proj table, blocks 204..339 weight split
// ---------------------------------------------------------------------------
__global__ void setup_kernel(const unsigned* __restrict__ ei_raw,
                             const float* __restrict__ emb,
                             const float* __restrict__ We,
                             const float* __restrict__ be,
                             const float* __restrict__ W1,
                             const float* __restrict__ W2) {
    int b = blockIdx.x;
    if (b < NBLK) {
        int i = b * 256 + threadIdx.x;
        if (i < N_NODES) g_cnt[i] = 0;
        if (b == 0 && threadIdx.x == 0) {
            unsigned acc = 0;
#pragma unroll
            for (int k = 0; k < 128; k++) acc |= ei_raw[2 * k + 1];
            g_idx64 = (acc == 0u) ? 1 : 0;
            g_barA = 0; g_barB = 0; g_barC = 0;
        }
    } else if (b < NBLK + 8) {
        int tid = (b - NBLK) * 256 + threadIdx.x;
        if (tid < 16 * HID) {
            int t = tid >> 7, j = tid & 127;
            float s = be[j];
#pragma unroll
            for (int d = 0; d < 8; d++)
                s = fmaf(emb[t * 8 + d], We[d * HID + j], s);
            ((float*)g_proj4)[tid] = s;
        }
    } else {
        int tid = (b - NBLK - 8) * 256 + threadIdx.x;
        if (tid < 2 * 128 * KSTR) {
            int mat = tid / (128 * KSTR);
            int rem = tid % (128 * KSTR);
            int n = rem / KSTR;
            int k = rem % KSTR;
            unsigned short hv = 0, lv = 0;
            if (k < 128) {
                const float* W = mat ? W2 : W1;
                float w = W[k * HID + n];
                __nv_bfloat16 h = __float2bfloat16(w);
                __nv_bfloat16 l = __float2bfloat16(w - __bfloat162float(h));
                hv = __bfloat16_as_ushort(h);
                lv = __bfloat16_as_ushort(l);
            }
            (mat ? g_w2h : g_w1h)[n * KSTR + k] = hv;
            (mat ? g_w2l : g_w1l)[n * KSTR + k] = lv;
        }
    }
}

// ---------------------------------------------------------------------------
// build: conv+hist -> scan -> scatter in ONE persistent kernel (196 blocks).
// ---------------------------------------------------------------------------
__global__ void __launch_bounds__(256)
build_kernel(const void* __restrict__ ei_v, const void* __restrict__ ea_v) {
    __shared__ int s[256];
    const int tid = threadIdx.x;
    const int b = blockIdx.x;
    const int gtid = b * 256 + tid;
    const int GSTRIDE = NBLK * 256;        // 50176

    if (g_idx64) {
        const long long* ei = (const long long*)ei_v;
        const long long* ea = (const long long*)ea_v;
#pragma unroll 4
        for (int e = gtid; e < N_EDGES; e += GSTRIDE) {
            int src = (int)ei[e], dst = (int)ei[N_EDGES + e];
            int h = (int)((ea[3LL * e] + 3 * ea[3LL * e + 1] + 7 * ea[3LL * e + 2]) & 15);
            g_srch[e] = ((unsigned)src << 4) | (unsigned)h;
            g_dst[e] = dst;
            atomicAdd(&g_cnt[dst], 1);
        }
    } else {
        const int* ei = (const int*)ei_v;
        const int* ea = (const int*)ea_v;
#pragma unroll 4
        for (int e = gtid; e < N_EDGES; e += GSTRIDE) {
            int src = ei[e], dst = ei[N_EDGES + e];
            int h = (ea[3 * e] + 3 * ea[3 * e + 1] + 7 * ea[3 * e + 2]) & 15;
            g_srch[e] = ((unsigned)src << 4) | (unsigned)h;
            g_dst[e] = dst;
            atomicAdd(&g_cnt[dst], 1);
        }
    }
    grid_barrier(&g_barA);

    int node = b * 256 + tid;
    int c = (node < N_NODES) ? g_cnt[node] : 0;
    s[tid] = c;
    __syncthreads();
#pragma unroll
    for (int d = 1; d < 256; d <<= 1) {
        int t = (tid >= d) ? s[tid - d] : 0;
        __syncthreads();
        s[tid] += t;
        __syncthreads();
    }
    int local_excl = s[tid] - c;
    if (tid == 255) g_bsum[b] = s[255];
    grid_barrier(&g_barB);

    s[tid] = (tid < b) ? g_bsum[tid] : 0;
    __syncthreads();
#pragma unroll
    for (int d = 128; d > 0; d >>= 1) {
        if (tid < d) s[tid] += s[tid + d];
        __syncthreads();
    }
    int bpre = s[0];
    if (node < N_NODES) {
        int o = local_excl + bpre;
        g_off[node] = o;
        g_cur[node] = o;
    }
    if (b == 0 && tid == 0) g_off[N_NODES] = N_EDGES;
    grid_barrier(&g_barC);

#pragma unroll 4
    for (int e = gtid; e < N_EDGES; e += GSTRIDE) {
        int pos = atomicAdd(&g_cur[g_dst[e]], 1);
        g_packed[pos] = g_srch[e];
    }
}

// ---------------------------------------------------------------------------
// aggregate: one warp per node, no atomics, 4-deep gather pipeline (proven)
// ---------------------------------------------------------------------------
__global__ void __launch_bounds__(256)
aggr_kernel(const float4* __restrict__ x4, const float* __restrict__ epsp) {
    int node = (blockIdx.x * blockDim.x + threadIdx.x) >> 5;
    int lane = threadIdx.x & 31;
    if (node >= N_NODES) return;

    int beg = g_off[node], end = g_off[node + 1];
    float4 acc = make_float4(0.f, 0.f, 0.f, 0.f);

    for (int e = beg; e < end; e += 4) {
        int m = end - e;
        unsigned pk[4];
#pragma unroll
        for (int j = 0; j < 4; j++)
            pk[j] = (j < m) ? __ldg(&g_packed[e + j]) : 0u;
        float4 xv[4], pv[4];
#pragma unroll
        for (int j = 0; j < 4; j++) {
            if (j < m) {
                xv[j] = __ldg(&x4[(size_t)(pk[j] >> 4) * 32 + lane]);
                pv[j] = __ldg(&g_proj4[(pk[j] & 15u) * 32 + lane]);
            }
        }
#pragma unroll
        for (int j = 0; j < 4; j++) {
            if (j < m) {
                acc.x += fmaxf(xv[j].x + pv[j].x, 0.f);
                acc.y += fmaxf(xv[j].y + pv[j].y, 0.f);
                acc.z += fmaxf(xv[j].z + pv[j].z, 0.f);
                acc.w += fmaxf(xv[j].w + pv[j].w, 0.f);
            }
        }
    }
    float e1 = 1.0f + __ldg(epsp);
    float4 xn = __ldg(&x4[(size_t)node * 32 + lane]);
    acc.x = fmaf(e1, xn.x, acc.x);
    acc.y = fmaf(e1, xn.y, acc.y);
    acc.z = fmaf(e1, xn.z, acc.z);
    acc.w = fmaf(e1, xn.w, acc.w);
    g_aggr4[(size_t)node * 32 + lane] = acc;
}

// ---------------------------------------------------------------------------
// MLP via mma.sync bf16x3 — 512 threads, 128 rows/CTA, ALL weights resident
// (209KB smem, 1 CTA/SM but 16 warps/SM). Warp grid 4Mx4N: 32x32 per warp.
// ---------------------------------------------------------------------------
#define SM_B1  0
#define SM_B2  512
#define SM_ZH  1024
#define SM_ZL  (SM_ZH + TILE_B)
#define SM_W1H (SM_ZL + TILE_B)
#define SM_W1L (SM_W1H + TILE_B)
#define SM_W2H (SM_W1L + TILE_B)
#define SM_W2L (SM_W2H + TILE_B)
#define SM_TOT (SM_W2L + TILE_B)     // 209920 bytes

__device__ __forceinline__ void gemm32x32(uint32_t sb, uint32_t wh, uint32_t wl,
                                          const uint32_t aB[2], const uint32_t bB[2],
                                          float acc[2][4][4]) {
#pragma unroll
    for (int ks = 0; ks < 8; ks++) {
        uint32_t k0b = ks * 32;
        uint32_t ah[2][4], al[2][4];
#pragma unroll
        for (int t = 0; t < 2; t++) {
            ldsm4(ah[t], sb + SM_ZH + aB[t] + k0b);
            ldsm4(al[t], sb + SM_ZL + aB[t] + k0b);
        }
#pragma unroll
        for (int u = 0; u < 2; u++) {
            uint32_t wH[4], wL[4];
            ldsm4(wH, sb + wh + bB[u] + k0b);
            ldsm4(wL, sb + wl + bB[u] + k0b);
#pragma unroll
            for (int t = 0; t < 2; t++) {
                mma_bf16(acc[t][2 * u],     ah[t], wH[0], wH[1]);
                mma_bf16(acc[t][2 * u],     ah[t], wL[0], wL[1]);
                mma_bf16(acc[t][2 * u],     al[t], wH[0], wH[1]);
                mma_bf16(acc[t][2 * u + 1], ah[t], wH[2], wH[3]);
                mma_bf16(acc[t][2 * u + 1], ah[t], wL[2], wL[3]);
                mma_bf16(acc[t][2 * u + 1], al[t], wH[2], wH[3]);
            }
        }
    }
}

__global__ void __launch_bounds__(512, 1)
mlp_mma_kernel(const float* __restrict__ b1, const float* __restrict__ b2,
               float* __restrict__ out) {
    extern __shared__ char smem[];
    const uint32_t sb = smem_u32(smem);
    const int tid = threadIdx.x, wid = tid >> 5, lane = tid & 31;
    const int base = blockIdx.x * 128;

    if (tid < 128) {
        ((float*)(smem + SM_B1))[tid] = b1[tid];
        ((float*)(smem + SM_B2))[tid] = b2[tid];
    }
    // weight tiles: straight copies (2176 uint4 each, 512 threads)
    {
        const uint4* s[4] = {(const uint4*)g_w1h, (const uint4*)g_w1l,
                             (const uint4*)g_w2h, (const uint4*)g_w2l};
        uint4* d[4] = {(uint4*)(smem + SM_W1H), (uint4*)(smem + SM_W1L),
                       (uint4*)(smem + SM_W2H), (uint4*)(smem + SM_W2L)};
#pragma unroll
        for (int a = 0; a < 4; a++)
            for (int i = tid; i < TILE_B / 16; i += 512) d[a][i] = s[a][i];
    }

    // z tile from aggr -> bf16 hi/lo (128 rows x 32 float4 = 4096)
#pragma unroll
    for (int it = 0; it < 8; it++) {
        int idx = tid + it * 512;
        int row = idx >> 5, c4 = idx & 31;
        int g = base + row;
        float4 v = make_float4(0.f, 0.f, 0.f, 0.f);
        if (g < N_NODES) v = g_aggr4[(size_t)g * 32 + c4];
        uint2 hv, lv;
        hv.x = splitpair(v.x, v.y, lv.x);
        hv.y = splitpair(v.z, v.w, lv.y);
        *(uint2*)(smem + SM_ZH + row * KSTRB + c4 * 8) = hv;
        *(uint2*)(smem + SM_ZL + row * KSTRB + c4 * 8) = lv;
    }
    __syncthreads();

    const int mw = wid & 3;            // 4 M groups of 32 rows
    const int nw = wid >> 2;           // 4 N groups of 32 cols
    uint32_t aB[2], bB[2];
#pragma unroll
    for (int t = 0; t < 2; t++)
        aB[t] = (uint32_t)(32 * mw + 16 * t + (lane & 15)) * KSTRB +
                ((lane & 16) ? 16 : 0);
    const int nrow = (lane & 7) + ((lane & 16) ? 8 : 0);
#pragma unroll
    for (int u = 0; u < 2; u++)
        bB[u] = (uint32_t)(32 * nw + 16 * u + nrow) * KSTRB +
                ((lane & 8) ? 16 : 0);

    const int g4 = lane >> 2, t4 = lane & 3;

    float acc[2][4][4];
#pragma unroll
    for (int t = 0; t < 2; t++)
#pragma unroll
        for (int j = 0; j < 4; j++)
#pragma unroll
            for (int i = 0; i < 4; i++) acc[t][j][i] = 0.f;

    gemm32x32(sb, SM_W1H, SM_W1L, aB, bB, acc);
    __syncthreads();   // all GEMM1 reads of z done before overwrite

    // epilogue1: h1 = relu(acc + b1) -> bf16 hi/lo back into z tiles
    {
        const float* b1s = (const float*)(smem + SM_B1);
#pragma unroll
        for (int t = 0; t < 2; t++) {
            int r0 = 32 * mw + 16 * t + g4;
#pragma unroll
            for (int j = 0; j < 4; j++) {
                int col = 32 * nw + 8 * j + 2 * t4;
                float v0 = fmaxf(acc[t][j][0] + b1s[col],     0.f);
                float v1 = fmaxf(acc[t][j][1] + b1s[col + 1], 0.f);
                float v2 = fmaxf(acc[t][j][2] + b1s[col],     0.f);
                float v3 = fmaxf(acc[t][j][3] + b1s[col + 1], 0.f);
                uint32_t l0, l1;
                uint32_t h0 = splitpair(v0, v1, l0);
                uint32_t h1 = splitpair(v2, v3, l1);
                uint32_t o0 = r0 * KSTRB + col * 2;
                uint32_t o1 = (r0 + 8) * KSTRB + col * 2;
                *(uint32_t*)(smem + SM_ZH + o0) = h0;
                *(uint32_t*)(smem + SM_ZL + o0) = l0;
                *(uint32_t*)(smem + SM_ZH + o1) = h1;
                *(uint32_t*)(smem + SM_ZL + o1) = l1;
                acc[t][j][0] = acc[t][j][1] = acc[t][j][2] = acc[t][j][3] = 0.f;
            }
        }
    }
    __syncthreads();

    gemm32x32(sb, SM_W2H, SM_W2L, aB, bB, acc);

    // epilogue2: out = acc + b2
    {
        const float* b2s = (const float*)(smem + SM_B2);
#pragma unroll
        for (int t = 0; t < 2; t++) {
            int r0 = 32 * mw + 16 * t + g4;
            int gr0 = base + r0, gr1 = gr0 + 8;
#pragma unroll
            for (int j = 0; j < 4; j++) {
                int col = 32 * nw + 8 * j + 2 * t4;
                if (gr0 < N_NODES) {
                    float2 v = make_float2(acc[t][j][0] + b2s[col],
                                           acc[t][j][1] + b2s[col + 1]);
                    *(float2*)&out[(size_t)gr0 * HID + col] = v;
                }
                if (gr1 < N_NODES) {
                    float2 v = make_float2(acc[t][j][2] + b2s[col],
                                           acc[t][j][3] + b2s[col + 1]);
                    *(float2*)&out[(size_t)gr1 * HID + col] = v;
                }
            }
        }
    }
}

// ---------------------------------------------------------------------------
extern "C" void kernel_launch(void* const* d_in, const int* in_sizes, int n_in,
                              void* d_out, int out_size) {
    const float* x   = (const float*)d_in[0];
    const void*  ei  = d_in[1];
    const void*  ea  = d_in[2];
    const float* emb = (const float*)d_in[3];
    const float* We  = (const float*)d_in[4];
    const float* be  = (const float*)d_in[5];
    const float* W1  = (const float*)d_in[6];
    const float* b1  = (const float*)d_in[7];
    const float* W2  = (const float*)d_in[8];
    const float* b2  = (const float*)d_in[9];
    const float* eps = (const float*)d_in[10];
    float*       out = (float*)d_out;

    cudaFuncSetAttribute(mlp_mma_kernel,
                         cudaFuncAttributeMaxDynamicSharedMemorySize, SM_TOT);

    setup_kernel<<<NBLK + 8 + 136, 256>>>((const unsigned*)ei, emb, We, be, W1, W2);
    build_kernel<<<NBLK, 256>>>(ei, ea);
    aggr_kernel<<<(N_NODES * 32 + 255) / 256, 256>>>((const float4*)x, eps);
    mlp_mma_kernel<<<(N_NODES + 127) / 128, 512, SM_TOT>>>(b1, b2, out);
}